// round 8
// baseline (speedup 1.0000x reference)
#include <cuda_runtime.h>
#include <cuda_bf16.h>
#include <cuda_fp16.h>
#include <cstdint>

#define TT 512
#define BB 256
#define HH 1024
#define KK 1024

// ---------------- device globals (static scratch; no allocations) ----------
__device__ __align__(16) unsigned short g_hhi[2][BB*HH];
__device__ __align__(16) unsigned short g_hlo[2][BB*HH];
__device__ unsigned g_count4[4 * 32];   // one counter per bt group, 128B apart
__device__ unsigned g_gen4[4 * 32];

// ---------------- helpers ---------------------------------------------------
__device__ __forceinline__ uint32_t smem_u32(const void* p) {
    uint32_t a;
    asm("{ .reg .u64 t; cvta.to.shared.u64 t, %1; cvt.u32.u64 %0, t; }"
        : "=r"(a) : "l"(p));
    return a;
}

__device__ __forceinline__ void ldsm4(uint32_t* r, uint32_t addr) {
    asm volatile("ldmatrix.sync.aligned.m8n8.x4.shared.b16 {%0,%1,%2,%3}, [%4];"
        : "=r"(r[0]), "=r"(r[1]), "=r"(r[2]), "=r"(r[3]) : "r"(addr));
}

// fp16 MMA
__device__ __forceinline__ void mma16816h(float* c, const uint32_t* a, const uint32_t* b) {
    asm volatile("mma.sync.aligned.m16n8k16.row.col.f32.f16.f16.f32 "
        "{%0,%1,%2,%3}, {%4,%5,%6,%7}, {%8,%9}, {%0,%1,%2,%3};"
        : "+f"(c[0]), "+f"(c[1]), "+f"(c[2]), "+f"(c[3])
        : "r"(a[0]), "r"(a[1]), "r"(a[2]), "r"(a[3]), "r"(b[0]), "r"(b[1]));
}

#define CP16(dst, src) \
    asm volatile("{\n\t.reg .u64 g;\n\tcvta.to.global.u64 g, %1;\n\t" \
                 "cp.async.cg.shared.global [%0], [g], 16;\n\t}" \
                 :: "r"(dst), "l"(src) : "memory")
#define CP_COMMIT() asm volatile("cp.async.commit_group;" ::: "memory")
#define CP_WAITN(n) asm volatile("cp.async.wait_group %0;" :: "n"(n) : "memory")

#define GROUP_BAR(id) asm volatile("bar.sync %0, %1;" :: "r"(id), "r"(128) : "memory")

__device__ __forceinline__ float tanh_fast(float x) {
    float e = __expf(2.0f * x);
    return 1.0f - 2.0f / (e + 1.0f);
}

// fp16 split
__device__ __forceinline__ void split2h(float a, float b, uint32_t& hi, uint32_t& lo) {
    __half ha = __float2half_rn(a);
    __half hb = __float2half_rn(b);
    float ra = a - __half2float(ha);
    float rb = b - __half2float(hb);
    __half la = __float2half_rn(ra);
    __half lb = __float2half_rn(rb);
    hi = (uint32_t)__half_as_ushort(ha) | ((uint32_t)__half_as_ushort(hb) << 16);
    lo = (uint32_t)__half_as_ushort(la) | ((uint32_t)__half_as_ushort(lb) << 16);
}

// fp16 pack (hi only)
__device__ __forceinline__ uint32_t pack2h(float a, float b) {
    __half ha = __float2half_rn(a);
    __half hb = __float2half_rn(b);
    return (uint32_t)__half_as_ushort(ha) | ((uint32_t)__half_as_ushort(hb) << 16);
}

// per-bt-group barrier: 32 participating blocks
__device__ __forceinline__ void group_sync(unsigned* cntp, unsigned* genp,
                                           unsigned base, unsigned gen) {
    __syncthreads();
    if (threadIdx.x == 0) {
        const unsigned target = base + gen;
        __threadfence();
        unsigned a = atomicAdd(cntp, 1u);
        if (a == 31u) {
            *(volatile unsigned*)cntp = 0u;
            __threadfence();
            atomicExch(genp, target);
        } else {
            while ((int)(*(volatile unsigned*)genp - target) < 0) __nanosleep(32);
        }
        __threadfence();
    }
    __syncthreads();
}

// ---------------------------------------------------------------------------
// Phase 1 (UNCHANGED from R7): XP = x @ Wx^T + bx, fp16 2-term.
// ---------------------------------------------------------------------------
#define P1_AH 0
#define P1_AL 10240
#define P1_BH 20480
#define P1_SMEM 30720

__global__ void __launch_bounds__(256, 1)
xproj_hmma(const float* __restrict__ X, const float* __restrict__ Wx,
           const float* __restrict__ bx, float* __restrict__ XP)
{
    extern __shared__ char smem[];
    __shared__ float bxs[128];
    const uint32_t sb = smem_u32(smem);
    const int tid = threadIdx.x;
    const int lane = tid & 31;
    const int w = tid >> 5;
    const int wm = w >> 2;
    const int wn = w & 3;
    const int n0 = blockIdx.x * 128;
    const int m0 = blockIdx.y * 128;

    if (tid < 128) bxs[tid] = bx[n0 + tid];

    const uint32_t aRel = (uint32_t)((wm * 64 + (lane & 15)) * 80 + (lane >> 4) * 16);
    const uint32_t bRel = (uint32_t)((wn * 32 + ((lane >> 4) & 1) * 8 + (lane & 7)) * 80
                                     + ((lane >> 3) & 1) * 16);

    float cc[4][4][4];
#pragma unroll
    for (int a = 0; a < 4; ++a)
#pragma unroll
        for (int b = 0; b < 4; ++b)
#pragma unroll
            for (int q = 0; q < 4; ++q) cc[a][b][q] = 0.0f;

    float4 va[4], vb[4];
#pragma unroll
    for (int i = 0; i < 4; ++i) {
        int u = tid + 256 * i;
        int row = u >> 3, k4 = u & 7;
        va[i] = *(const float4*)(X + (size_t)(m0 + row) * KK + k4 * 4);
        vb[i] = *(const float4*)(Wx + (size_t)(n0 + row) * KK + k4 * 4);
    }

#pragma unroll 1
    for (int c = 0; c < 32; ++c) {
#pragma unroll
        for (int i = 0; i < 4; ++i) {
            int u = tid + 256 * i;
            int row = u >> 3, k4 = u & 7;
            uint32_t off = (uint32_t)(row * 80 + k4 * 8);
            uint2 hi, lo;
            split2h(va[i].x, va[i].y, hi.x, lo.x);
            split2h(va[i].z, va[i].w, hi.y, lo.y);
            *(uint2*)(smem + P1_AH + off) = hi;
            *(uint2*)(smem + P1_AL + off) = lo;
            uint2 bhp;
            bhp.x = pack2h(vb[i].x, vb[i].y);
            bhp.y = pack2h(vb[i].z, vb[i].w);
            *(uint2*)(smem + P1_BH + off) = bhp;
        }
        __syncthreads();

        if (c < 31) {
            const int k0 = (c + 1) * 32;
#pragma unroll
            for (int i = 0; i < 4; ++i) {
                int u = tid + 256 * i;
                int row = u >> 3, k4 = u & 7;
                va[i] = *(const float4*)(X + (size_t)(m0 + row) * KK + k0 + k4 * 4);
                vb[i] = *(const float4*)(Wx + (size_t)(n0 + row) * KK + k0 + k4 * 4);
            }
        }

#pragma unroll
        for (int kk = 0; kk < 2; ++kk) {
            const uint32_t ka = kk * 32;
            uint32_t ah[4][4], al[4][4], bh[8];
#pragma unroll
            for (int mi = 0; mi < 4; ++mi) {
                ldsm4(ah[mi], sb + P1_AH + aRel + mi * 1280 + ka);
                ldsm4(al[mi], sb + P1_AL + aRel + mi * 1280 + ka);
            }
            ldsm4(bh,     sb + P1_BH + bRel + ka);
            ldsm4(bh + 4, sb + P1_BH + bRel + 1280 + ka);
#pragma unroll
            for (int mi = 0; mi < 4; ++mi)
#pragma unroll
                for (int ni = 0; ni < 4; ++ni) {
                    mma16816h(cc[mi][ni], ah[mi], bh + 2 * ni);
                    mma16816h(cc[mi][ni], al[mi], bh + 2 * ni);
                }
        }
        __syncthreads();
    }

#pragma unroll
    for (int mi = 0; mi < 4; ++mi)
#pragma unroll
        for (int ni = 0; ni < 4; ++ni)
#pragma unroll
            for (int p = 0; p < 2; ++p) {
                int row = wm * 64 + mi * 16 + (lane >> 2) + p * 8;
                int col = wn * 32 + ni * 8 + (lane & 3) * 2;
                float2 v;
                v.x = cc[mi][ni][2 * p]     + bxs[col];
                v.y = cc[mi][ni][2 * p + 1] + bxs[col + 1];
                *(float2*)(XP + (size_t)(m0 + row) * HH + n0 + col) = v;
            }
}

// ---------------------------------------------------------------------------
// Phase 2 v4: fp16 2-term recurrence: (h_hi + h_lo) @ Wh_hi.
// Structure identical to R6 otherwise. Wh resident hi-only (66KB).
// ---------------------------------------------------------------------------
#define P2_NBLK 128
#define P2_WH_H 0
#define P2_A    66048             // + kg*49152 + buf*16384 (+8192 for lo)
#define P2_SMEM 164352

__global__ void __launch_bounds__(256, 1)
rnn_hmma(const float* __restrict__ Wh, const float* __restrict__ bh,
         float* __restrict__ out)
{
    extern __shared__ char smem[];
    __shared__ float bhs[32];
    __shared__ unsigned sbase;
    const uint32_t sb = smem_u32(smem);
    const int tid = threadIdx.x;
    const int lane = tid & 31;
    const int w = tid >> 5;
    const int kg = w >> 2;           // k-group: 0 -> k[0,512), 1 -> k[512,1024)
    const int wl = w & 3;
    const int wm = wl >> 1;          // 0..1 (32 m rows)
    const int wn = wl & 1;           // 0..1 (16 n cols)
    const int tig = tid & 127;       // thread id within group
    const int bidx = blockIdx.x;
    const int jt = bidx & 31, bt = bidx >> 5;
    const int j0 = jt * 32, b0 = bt * 64;

    unsigned* cntp = &g_count4[bt * 32];
    unsigned* genp = &g_gen4[bt * 32];

    float* hfinal = out;
    float* hall = out + (size_t)BB * HH;

    if (tid == 0) sbase = *(volatile unsigned*)genp;
    if (tid < 32) bhs[tid] = bh[j0 + tid];

    // load resident Wh tile (fp16 hi only): 32 rows x 1024 k, rows padded 2064B
#pragma unroll 1
    for (int i = tid; i < 32 * 256; i += 256) {
        int row = i >> 8, k4 = i & 255;
        float4 v = *(const float4*)(Wh + (size_t)(j0 + row) * KK + k4 * 4);
        uint2 hp;
        hp.x = pack2h(v.x, v.y);
        hp.y = pack2h(v.z, v.w);
        *(uint2*)(smem + P2_WH_H + (uint32_t)(row * 2064 + k4 * 8)) = hp;
    }

    // zero this bt group's t=0 hidden-state rows (32 blocks share the slice)
    {
        uint4 z = make_uint4(0, 0, 0, 0);
        const int sliceBase = b0 * HH / 8;      // uint4 index of row b0
        for (int i = jt * 256 + tid; i < 64 * HH / 8; i += 32 * 256) {
            ((uint4*)g_hhi[0])[sliceBase + i] = z;
            ((uint4*)g_hlo[0])[sliceBase + i] = z;
        }
    }
    __syncthreads();
    const unsigned base = sbase;
    unsigned gen = 1;
    group_sync(cntp, genp, base, gen++);

    // ldmatrix A addressing (swizzled 128B rows)
    const uint32_t aLin = (uint32_t)((wm * 32 + (lane & 15)) * 128 + (lane >> 4) * 16);
    const uint32_t aXor = (uint32_t)((lane & 7) << 4);
    // ldmatrix B addressing (2064B padded rows)
    const uint32_t bRel = (uint32_t)((wn * 16 + ((lane >> 4) & 1) * 8 + (lane & 7)) * 2064
                                     + ((lane >> 3) & 1) * 16);
    const uint32_t kgOff = (uint32_t)(kg * 1024);   // byte offset into Wh rows
    // cp.async coords
    const int cprow0 = tig >> 3, cpseg = tig & 7;
    const uint32_t aBase = sb + P2_A + (uint32_t)(kg * 49152);
    const size_t kSrc0 = (size_t)kg * 512 + cpseg * 8;

    // epilogue/partial fragment coordinates
    int erow[2][2], ecol[2];
#pragma unroll
    for (int mi = 0; mi < 2; ++mi)
#pragma unroll
        for (int p = 0; p < 2; ++p)
            erow[mi][p] = wm * 32 + mi * 16 + (lane >> 2) + p * 8;
#pragma unroll
    for (int ni = 0; ni < 2; ++ni)
        ecol[ni] = wn * 16 + ni * 8 + (lane & 3) * 2;
    float* psm = (float*)(smem + P2_A + 49152);   // partial exchange (group1 buf0)

#pragma unroll 1
    for (int t = 0; t < TT; ++t) {
        const unsigned short* hrh = g_hhi[t & 1];
        const unsigned short* hrl = g_hlo[t & 1];
        unsigned short* hwh = g_hhi[(t & 1) ^ 1];
        unsigned short* hwl = g_hlo[(t & 1) ^ 1];
        float* hat = hall + (size_t)t * (BB * HH);

        // xp prefetch into registers (group 0 only; consumed in epilogue)
        float2 xpv[2][2][2];
        if (kg == 0) {
#pragma unroll
            for (int mi = 0; mi < 2; ++mi)
#pragma unroll
                for (int ni = 0; ni < 2; ++ni)
#pragma unroll
                    for (int p = 0; p < 2; ++p)
                        xpv[mi][ni][p] = *(const float2*)(hat +
                            (size_t)(b0 + erow[mi][p]) * HH + j0 + ecol[ni]);
        }

        float cc[2][2][4];
#pragma unroll
        for (int a = 0; a < 2; ++a)
#pragma unroll
            for (int b = 0; b < 2; ++b)
#pragma unroll
                for (int q = 0; q < 4; ++q) cc[a][b][q] = 0.0f;

        // prologue: issue chunks 0 and 1
#pragma unroll
        for (int pc = 0; pc < 2; ++pc) {
            const uint32_t bufb = aBase + (uint32_t)(pc * 16384);
#pragma unroll
            for (int i = 0; i < 4; ++i) {
                int row = cprow0 + 16 * i;
                uint32_t dst = bufb + (((uint32_t)(row * 128 + cpseg * 16)) ^ ((uint32_t)(row & 7) << 4));
                size_t src = (size_t)(b0 + row) * KK + kSrc0 + pc * 64;
                CP16(dst, hrh + src);
                CP16(dst + 8192, hrl + src);
            }
            CP_COMMIT();
        }

#pragma unroll 1
        for (int c = 0; c < 8; ++c) {
            if (c < 7) { CP_WAITN(1); } else { CP_WAITN(0); }
            GROUP_BAR(kg + 1);
            if (c + 2 < 8) {
                const uint32_t bufb = aBase + (uint32_t)(((c + 2) % 3) * 16384);
#pragma unroll
                for (int i = 0; i < 4; ++i) {
                    int row = cprow0 + 16 * i;
                    uint32_t dst = bufb + (((uint32_t)(row * 128 + cpseg * 16)) ^ ((uint32_t)(row & 7) << 4));
                    size_t src = (size_t)(b0 + row) * KK + kSrc0 + (c + 2) * 64;
                    CP16(dst, hrh + src);
                    CP16(dst + 8192, hrl + src);
                }
                CP_COMMIT();
            }

            const uint32_t aH = aBase + (uint32_t)((c % 3) * 16384);
            const uint32_t aL = aH + 8192;
            const uint32_t kOff = kgOff + (uint32_t)(c * 128);
#pragma unroll
            for (int kk = 0; kk < 4; ++kk) {
                const uint32_t ka = kk * 32;
                uint32_t ah0[4], ah1[4], al0[4], al1[4], bhf[4];
                ldsm4(ah0, aH + ((aLin + ka) ^ aXor));
                ldsm4(ah1, aH + ((aLin + 2048 + ka) ^ aXor));
                ldsm4(al0, aL + ((aLin + ka) ^ aXor));
                ldsm4(al1, aL + ((aLin + 2048 + ka) ^ aXor));
                ldsm4(bhf, sb + P2_WH_H + bRel + kOff + ka);
#pragma unroll
                for (int ni = 0; ni < 2; ++ni) {
                    mma16816h(cc[0][ni], ah0, bhf + 2 * ni);
                    mma16816h(cc[0][ni], al0, bhf + 2 * ni);
                    mma16816h(cc[1][ni], ah1, bhf + 2 * ni);
                    mma16816h(cc[1][ni], al1, bhf + 2 * ni);
                }
            }
        }

        // group 1 publishes partials
        if (kg == 1) {
#pragma unroll
            for (int mi = 0; mi < 2; ++mi)
#pragma unroll
                for (int ni = 0; ni < 2; ++ni)
#pragma unroll
                    for (int p = 0; p < 2; ++p)
                        *(float2*)&psm[erow[mi][p] * 32 + ecol[ni]] =
                            make_float2(cc[mi][ni][2 * p], cc[mi][ni][2 * p + 1]);
        }
        __syncthreads();

        // group 0 combines + epilogue
        if (kg == 0) {
#pragma unroll
            for (int mi = 0; mi < 2; ++mi)
#pragma unroll
                for (int ni = 0; ni < 2; ++ni)
#pragma unroll
                    for (int p = 0; p < 2; ++p) {
                        const int row = erow[mi][p], col = ecol[ni];
                        float2 pp = *(float2*)&psm[row * 32 + col];
                        size_t idx = (size_t)(b0 + row) * HH + j0 + col;
                        float v0 = tanh_fast(cc[mi][ni][2 * p]     + pp.x + bhs[col]     + xpv[mi][ni][p].x);
                        float v1 = tanh_fast(cc[mi][ni][2 * p + 1] + pp.y + bhs[col + 1] + xpv[mi][ni][p].y);
                        *(float2*)(hat + idx) = make_float2(v0, v1);
                        if (t == TT - 1) *(float2*)(hfinal + idx) = make_float2(v0, v1);
                        uint32_t hi, lo;
                        split2h(v0, v1, hi, lo);
                        *(uint32_t*)(hwh + idx) = hi;
                        *(uint32_t*)(hwl + idx) = lo;
                    }
        }

        group_sync(cntp, genp, base, gen++);
    }
}

// ---------------------------------------------------------------------------
extern "C" void kernel_launch(void* const* d_in, const int* in_sizes, int n_in,
                              void* d_out, int out_size)
{
    (void)in_sizes; (void)n_in; (void)out_size;
    const float* x  = (const float*)d_in[0];
    const float* Wx = (const float*)d_in[1];
    const float* bx = (const float*)d_in[2];
    const float* Wh = (const float*)d_in[3];
    const float* bh = (const float*)d_in[4];
    float* out = (float*)d_out;
    float* xp = out + (size_t)BB * HH;   // h_all region doubles as xp scratch

    cudaFuncSetAttribute(xproj_hmma, cudaFuncAttributeMaxDynamicSharedMemorySize, P1_SMEM);
    cudaFuncSetAttribute(rnn_hmma,  cudaFuncAttributeMaxDynamicSharedMemorySize, P2_SMEM);

    dim3 g1(HH / 128, (TT * BB) / 128);
    xproj_hmma<<<g1, 256, P1_SMEM>>>(x, Wx, bx, xp);
    rnn_hmma<<<P2_NBLK, 256, P2_SMEM>>>(Wh, bh, out);
}

// round 9
// speedup vs baseline: 1.5333x; 1.5333x over previous
#include <cuda_runtime.h>
#include <cuda_bf16.h>
#include <cuda_fp16.h>
#include <cstdint>

// R9 = R8 resubmitted unchanged: discriminating re-bench for the run-level
// slowdown hypothesis (phase 1 was byte-identical in R7/R8 yet differed 55%).

#define TT 512
#define BB 256
#define HH 1024
#define KK 1024

// ---------------- device globals (static scratch; no allocations) ----------
__device__ __align__(16) unsigned short g_hhi[2][BB*HH];
__device__ __align__(16) unsigned short g_hlo[2][BB*HH];
__device__ unsigned g_count4[4 * 32];   // one counter per bt group, 128B apart
__device__ unsigned g_gen4[4 * 32];

// ---------------- helpers ---------------------------------------------------
__device__ __forceinline__ uint32_t smem_u32(const void* p) {
    uint32_t a;
    asm("{ .reg .u64 t; cvta.to.shared.u64 t, %1; cvt.u32.u64 %0, t; }"
        : "=r"(a) : "l"(p));
    return a;
}

__device__ __forceinline__ void ldsm4(uint32_t* r, uint32_t addr) {
    asm volatile("ldmatrix.sync.aligned.m8n8.x4.shared.b16 {%0,%1,%2,%3}, [%4];"
        : "=r"(r[0]), "=r"(r[1]), "=r"(r[2]), "=r"(r[3]) : "r"(addr));
}

// fp16 MMA
__device__ __forceinline__ void mma16816h(float* c, const uint32_t* a, const uint32_t* b) {
    asm volatile("mma.sync.aligned.m16n8k16.row.col.f32.f16.f16.f32 "
        "{%0,%1,%2,%3}, {%4,%5,%6,%7}, {%8,%9}, {%0,%1,%2,%3};"
        : "+f"(c[0]), "+f"(c[1]), "+f"(c[2]), "+f"(c[3])
        : "r"(a[0]), "r"(a[1]), "r"(a[2]), "r"(a[3]), "r"(b[0]), "r"(b[1]));
}

#define CP16(dst, src) \
    asm volatile("{\n\t.reg .u64 g;\n\tcvta.to.global.u64 g, %1;\n\t" \
                 "cp.async.cg.shared.global [%0], [g], 16;\n\t}" \
                 :: "r"(dst), "l"(src) : "memory")
#define CP_COMMIT() asm volatile("cp.async.commit_group;" ::: "memory")
#define CP_WAITN(n) asm volatile("cp.async.wait_group %0;" :: "n"(n) : "memory")

#define GROUP_BAR(id) asm volatile("bar.sync %0, %1;" :: "r"(id), "r"(128) : "memory")

__device__ __forceinline__ float tanh_fast(float x) {
    float e = __expf(2.0f * x);
    return 1.0f - 2.0f / (e + 1.0f);
}

// fp16 split
__device__ __forceinline__ void split2h(float a, float b, uint32_t& hi, uint32_t& lo) {
    __half ha = __float2half_rn(a);
    __half hb = __float2half_rn(b);
    float ra = a - __half2float(ha);
    float rb = b - __half2float(hb);
    __half la = __float2half_rn(ra);
    __half lb = __float2half_rn(rb);
    hi = (uint32_t)__half_as_ushort(ha) | ((uint32_t)__half_as_ushort(hb) << 16);
    lo = (uint32_t)__half_as_ushort(la) | ((uint32_t)__half_as_ushort(lb) << 16);
}

// fp16 pack (hi only)
__device__ __forceinline__ uint32_t pack2h(float a, float b) {
    __half ha = __float2half_rn(a);
    __half hb = __float2half_rn(b);
    return (uint32_t)__half_as_ushort(ha) | ((uint32_t)__half_as_ushort(hb) << 16);
}

// per-bt-group barrier: 32 participating blocks
__device__ __forceinline__ void group_sync(unsigned* cntp, unsigned* genp,
                                           unsigned base, unsigned gen) {
    __syncthreads();
    if (threadIdx.x == 0) {
        const unsigned target = base + gen;
        __threadfence();
        unsigned a = atomicAdd(cntp, 1u);
        if (a == 31u) {
            *(volatile unsigned*)cntp = 0u;
            __threadfence();
            atomicExch(genp, target);
        } else {
            while ((int)(*(volatile unsigned*)genp - target) < 0) __nanosleep(32);
        }
        __threadfence();
    }
    __syncthreads();
}

// ---------------------------------------------------------------------------
// Phase 1: XP = x @ Wx^T + bx, fp16 2-term: (xh + xl) @ Wxh.
// ---------------------------------------------------------------------------
#define P1_AH 0
#define P1_AL 10240
#define P1_BH 20480
#define P1_SMEM 30720

__global__ void __launch_bounds__(256, 1)
xproj_hmma(const float* __restrict__ X, const float* __restrict__ Wx,
           const float* __restrict__ bx, float* __restrict__ XP)
{
    extern __shared__ char smem[];
    __shared__ float bxs[128];
    const uint32_t sb = smem_u32(smem);
    const int tid = threadIdx.x;
    const int lane = tid & 31;
    const int w = tid >> 5;
    const int wm = w >> 2;
    const int wn = w & 3;
    const int n0 = blockIdx.x * 128;
    const int m0 = blockIdx.y * 128;

    if (tid < 128) bxs[tid] = bx[n0 + tid];

    const uint32_t aRel = (uint32_t)((wm * 64 + (lane & 15)) * 80 + (lane >> 4) * 16);
    const uint32_t bRel = (uint32_t)((wn * 32 + ((lane >> 4) & 1) * 8 + (lane & 7)) * 80
                                     + ((lane >> 3) & 1) * 16);

    float cc[4][4][4];
#pragma unroll
    for (int a = 0; a < 4; ++a)
#pragma unroll
        for (int b = 0; b < 4; ++b)
#pragma unroll
            for (int q = 0; q < 4; ++q) cc[a][b][q] = 0.0f;

    float4 va[4], vb[4];
#pragma unroll
    for (int i = 0; i < 4; ++i) {
        int u = tid + 256 * i;
        int row = u >> 3, k4 = u & 7;
        va[i] = *(const float4*)(X + (size_t)(m0 + row) * KK + k4 * 4);
        vb[i] = *(const float4*)(Wx + (size_t)(n0 + row) * KK + k4 * 4);
    }

#pragma unroll 1
    for (int c = 0; c < 32; ++c) {
#pragma unroll
        for (int i = 0; i < 4; ++i) {
            int u = tid + 256 * i;
            int row = u >> 3, k4 = u & 7;
            uint32_t off = (uint32_t)(row * 80 + k4 * 8);
            uint2 hi, lo;
            split2h(va[i].x, va[i].y, hi.x, lo.x);
            split2h(va[i].z, va[i].w, hi.y, lo.y);
            *(uint2*)(smem + P1_AH + off) = hi;
            *(uint2*)(smem + P1_AL + off) = lo;
            uint2 bhp;
            bhp.x = pack2h(vb[i].x, vb[i].y);
            bhp.y = pack2h(vb[i].z, vb[i].w);
            *(uint2*)(smem + P1_BH + off) = bhp;
        }
        __syncthreads();

        if (c < 31) {
            const int k0 = (c + 1) * 32;
#pragma unroll
            for (int i = 0; i < 4; ++i) {
                int u = tid + 256 * i;
                int row = u >> 3, k4 = u & 7;
                va[i] = *(const float4*)(X + (size_t)(m0 + row) * KK + k0 + k4 * 4);
                vb[i] = *(const float4*)(Wx + (size_t)(n0 + row) * KK + k0 + k4 * 4);
            }
        }

#pragma unroll
        for (int kk = 0; kk < 2; ++kk) {
            const uint32_t ka = kk * 32;
            uint32_t ah[4][4], al[4][4], bh[8];
#pragma unroll
            for (int mi = 0; mi < 4; ++mi) {
                ldsm4(ah[mi], sb + P1_AH + aRel + mi * 1280 + ka);
                ldsm4(al[mi], sb + P1_AL + aRel + mi * 1280 + ka);
            }
            ldsm4(bh,     sb + P1_BH + bRel + ka);
            ldsm4(bh + 4, sb + P1_BH + bRel + 1280 + ka);
#pragma unroll
            for (int mi = 0; mi < 4; ++mi)
#pragma unroll
                for (int ni = 0; ni < 4; ++ni) {
                    mma16816h(cc[mi][ni], ah[mi], bh + 2 * ni);
                    mma16816h(cc[mi][ni], al[mi], bh + 2 * ni);
                }
        }
        __syncthreads();
    }

#pragma unroll
    for (int mi = 0; mi < 4; ++mi)
#pragma unroll
        for (int ni = 0; ni < 4; ++ni)
#pragma unroll
            for (int p = 0; p < 2; ++p) {
                int row = wm * 64 + mi * 16 + (lane >> 2) + p * 8;
                int col = wn * 32 + ni * 8 + (lane & 3) * 2;
                float2 v;
                v.x = cc[mi][ni][2 * p]     + bxs[col];
                v.y = cc[mi][ni][2 * p + 1] + bxs[col + 1];
                *(float2*)(XP + (size_t)(m0 + row) * HH + n0 + col) = v;
            }
}

// ---------------------------------------------------------------------------
// Phase 2: fp16 2-term recurrence: (h_hi + h_lo) @ Wh_hi. Wh resident (66KB).
// ---------------------------------------------------------------------------
#define P2_NBLK 128
#define P2_WH_H 0
#define P2_A    66048             // + kg*49152 + buf*16384 (+8192 for lo)
#define P2_SMEM 164352

__global__ void __launch_bounds__(256, 1)
rnn_hmma(const float* __restrict__ Wh, const float* __restrict__ bh,
         float* __restrict__ out)
{
    extern __shared__ char smem[];
    __shared__ float bhs[32];
    __shared__ unsigned sbase;
    const uint32_t sb = smem_u32(smem);
    const int tid = threadIdx.x;
    const int lane = tid & 31;
    const int w = tid >> 5;
    const int kg = w >> 2;           // k-group: 0 -> k[0,512), 1 -> k[512,1024)
    const int wl = w & 3;
    const int wm = wl >> 1;          // 0..1 (32 m rows)
    const int wn = wl & 1;           // 0..1 (16 n cols)
    const int tig = tid & 127;       // thread id within group
    const int bidx = blockIdx.x;
    const int jt = bidx & 31, bt = bidx >> 5;
    const int j0 = jt * 32, b0 = bt * 64;

    unsigned* cntp = &g_count4[bt * 32];
    unsigned* genp = &g_gen4[bt * 32];

    float* hfinal = out;
    float* hall = out + (size_t)BB * HH;

    if (tid == 0) sbase = *(volatile unsigned*)genp;
    if (tid < 32) bhs[tid] = bh[j0 + tid];

    // load resident Wh tile (fp16 hi only): 32 rows x 1024 k, rows padded 2064B
#pragma unroll 1
    for (int i = tid; i < 32 * 256; i += 256) {
        int row = i >> 8, k4 = i & 255;
        float4 v = *(const float4*)(Wh + (size_t)(j0 + row) * KK + k4 * 4);
        uint2 hp;
        hp.x = pack2h(v.x, v.y);
        hp.y = pack2h(v.z, v.w);
        *(uint2*)(smem + P2_WH_H + (uint32_t)(row * 2064 + k4 * 8)) = hp;
    }

    // zero this bt group's t=0 hidden-state rows (32 blocks share the slice)
    {
        uint4 z = make_uint4(0, 0, 0, 0);
        const int sliceBase = b0 * HH / 8;      // uint4 index of row b0
        for (int i = jt * 256 + tid; i < 64 * HH / 8; i += 32 * 256) {
            ((uint4*)g_hhi[0])[sliceBase + i] = z;
            ((uint4*)g_hlo[0])[sliceBase + i] = z;
        }
    }
    __syncthreads();
    const unsigned base = sbase;
    unsigned gen = 1;
    group_sync(cntp, genp, base, gen++);

    // ldmatrix A addressing (swizzled 128B rows)
    const uint32_t aLin = (uint32_t)((wm * 32 + (lane & 15)) * 128 + (lane >> 4) * 16);
    const uint32_t aXor = (uint32_t)((lane & 7) << 4);
    // ldmatrix B addressing (2064B padded rows)
    const uint32_t bRel = (uint32_t)((wn * 16 + ((lane >> 4) & 1) * 8 + (lane & 7)) * 2064
                                     + ((lane >> 3) & 1) * 16);
    const uint32_t kgOff = (uint32_t)(kg * 1024);   // byte offset into Wh rows
    // cp.async coords
    const int cprow0 = tig >> 3, cpseg = tig & 7;
    const uint32_t aBase = sb + P2_A + (uint32_t)(kg * 49152);
    const size_t kSrc0 = (size_t)kg * 512 + cpseg * 8;

    // epilogue/partial fragment coordinates
    int erow[2][2], ecol[2];
#pragma unroll
    for (int mi = 0; mi < 2; ++mi)
#pragma unroll
        for (int p = 0; p < 2; ++p)
            erow[mi][p] = wm * 32 + mi * 16 + (lane >> 2) + p * 8;
#pragma unroll
    for (int ni = 0; ni < 2; ++ni)
        ecol[ni] = wn * 16 + ni * 8 + (lane & 3) * 2;
    float* psm = (float*)(smem + P2_A + 49152);   // partial exchange (group1 buf0)

#pragma unroll 1
    for (int t = 0; t < TT; ++t) {
        const unsigned short* hrh = g_hhi[t & 1];
        const unsigned short* hrl = g_hlo[t & 1];
        unsigned short* hwh = g_hhi[(t & 1) ^ 1];
        unsigned short* hwl = g_hlo[(t & 1) ^ 1];
        float* hat = hall + (size_t)t * (BB * HH);

        // xp prefetch into registers (group 0 only; consumed in epilogue)
        float2 xpv[2][2][2];
        if (kg == 0) {
#pragma unroll
            for (int mi = 0; mi < 2; ++mi)
#pragma unroll
                for (int ni = 0; ni < 2; ++ni)
#pragma unroll
                    for (int p = 0; p < 2; ++p)
                        xpv[mi][ni][p] = *(const float2*)(hat +
                            (size_t)(b0 + erow[mi][p]) * HH + j0 + ecol[ni]);
        }

        float cc[2][2][4];
#pragma unroll
        for (int a = 0; a < 2; ++a)
#pragma unroll
            for (int b = 0; b < 2; ++b)
#pragma unroll
                for (int q = 0; q < 4; ++q) cc[a][b][q] = 0.0f;

        // prologue: issue chunks 0 and 1
#pragma unroll
        for (int pc = 0; pc < 2; ++pc) {
            const uint32_t bufb = aBase + (uint32_t)(pc * 16384);
#pragma unroll
            for (int i = 0; i < 4; ++i) {
                int row = cprow0 + 16 * i;
                uint32_t dst = bufb + (((uint32_t)(row * 128 + cpseg * 16)) ^ ((uint32_t)(row & 7) << 4));
                size_t src = (size_t)(b0 + row) * KK + kSrc0 + pc * 64;
                CP16(dst, hrh + src);
                CP16(dst + 8192, hrl + src);
            }
            CP_COMMIT();
        }

#pragma unroll 1
        for (int c = 0; c < 8; ++c) {
            if (c < 7) { CP_WAITN(1); } else { CP_WAITN(0); }
            GROUP_BAR(kg + 1);
            if (c + 2 < 8) {
                const uint32_t bufb = aBase + (uint32_t)(((c + 2) % 3) * 16384);
#pragma unroll
                for (int i = 0; i < 4; ++i) {
                    int row = cprow0 + 16 * i;
                    uint32_t dst = bufb + (((uint32_t)(row * 128 + cpseg * 16)) ^ ((uint32_t)(row & 7) << 4));
                    size_t src = (size_t)(b0 + row) * KK + kSrc0 + (c + 2) * 64;
                    CP16(dst, hrh + src);
                    CP16(dst + 8192, hrl + src);
                }
                CP_COMMIT();
            }

            const uint32_t aH = aBase + (uint32_t)((c % 3) * 16384);
            const uint32_t aL = aH + 8192;
            const uint32_t kOff = kgOff + (uint32_t)(c * 128);
#pragma unroll
            for (int kk = 0; kk < 4; ++kk) {
                const uint32_t ka = kk * 32;
                uint32_t ah0[4], ah1[4], al0[4], al1[4], bhf[4];
                ldsm4(ah0, aH + ((aLin + ka) ^ aXor));
                ldsm4(ah1, aH + ((aLin + 2048 + ka) ^ aXor));
                ldsm4(al0, aL + ((aLin + ka) ^ aXor));
                ldsm4(al1, aL + ((aLin + 2048 + ka) ^ aXor));
                ldsm4(bhf, sb + P2_WH_H + bRel + kOff + ka);
#pragma unroll
                for (int ni = 0; ni < 2; ++ni) {
                    mma16816h(cc[0][ni], ah0, bhf + 2 * ni);
                    mma16816h(cc[0][ni], al0, bhf + 2 * ni);
                    mma16816h(cc[1][ni], ah1, bhf + 2 * ni);
                    mma16816h(cc[1][ni], al1, bhf + 2 * ni);
                }
            }
        }

        // group 1 publishes partials
        if (kg == 1) {
#pragma unroll
            for (int mi = 0; mi < 2; ++mi)
#pragma unroll
                for (int ni = 0; ni < 2; ++ni)
#pragma unroll
                    for (int p = 0; p < 2; ++p)
                        *(float2*)&psm[erow[mi][p] * 32 + ecol[ni]] =
                            make_float2(cc[mi][ni][2 * p], cc[mi][ni][2 * p + 1]);
        }
        __syncthreads();

        // group 0 combines + epilogue
        if (kg == 0) {
#pragma unroll
            for (int mi = 0; mi < 2; ++mi)
#pragma unroll
                for (int ni = 0; ni < 2; ++ni)
#pragma unroll
                    for (int p = 0; p < 2; ++p) {
                        const int row = erow[mi][p], col = ecol[ni];
                        float2 pp = *(float2*)&psm[row * 32 + col];
                        size_t idx = (size_t)(b0 + row) * HH + j0 + col;
                        float v0 = tanh_fast(cc[mi][ni][2 * p]     + pp.x + bhs[col]     + xpv[mi][ni][p].x);
                        float v1 = tanh_fast(cc[mi][ni][2 * p + 1] + pp.y + bhs[col + 1] + xpv[mi][ni][p].y);
                        *(float2*)(hat + idx) = make_float2(v0, v1);
                        if (t == TT - 1) *(float2*)(hfinal + idx) = make_float2(v0, v1);
                        uint32_t hi, lo;
                        split2h(v0, v1, hi, lo);
                        *(uint32_t*)(hwh + idx) = hi;
                        *(uint32_t*)(hwl + idx) = lo;
                    }
        }

        group_sync(cntp, genp, base, gen++);
    }
}

// ---------------------------------------------------------------------------
extern "C" void kernel_launch(void* const* d_in, const int* in_sizes, int n_in,
                              void* d_out, int out_size)
{
    (void)in_sizes; (void)n_in; (void)out_size;
    const float* x  = (const float*)d_in[0];
    const float* Wx = (const float*)d_in[1];
    const float* bx = (const float*)d_in[2];
    const float* Wh = (const float*)d_in[3];
    const float* bh = (const float*)d_in[4];
    float* out = (float*)d_out;
    float* xp = out + (size_t)BB * HH;   // h_all region doubles as xp scratch

    cudaFuncSetAttribute(xproj_hmma, cudaFuncAttributeMaxDynamicSharedMemorySize, P1_SMEM);
    cudaFuncSetAttribute(rnn_hmma,  cudaFuncAttributeMaxDynamicSharedMemorySize, P2_SMEM);

    dim3 g1(HH / 128, (TT * BB) / 128);
    xproj_hmma<<<g1, 256, P1_SMEM>>>(x, Wx, bx, xp);
    rnn_hmma<<<P2_NBLK, 256, P2_SMEM>>>(Wh, bh, out);
}